// round 3
// baseline (speedup 1.0000x reference)
#include <cuda_runtime.h>
#include <cuda_bf16.h>

// ShiftImgPreprocessor: out[b,t,c,i,j] = img[b,t,c, clamp(i+sy-PAD,0,H-1),
//                                              clamp(j+sx-PAD,0,W-1)] / 255 - 0.5
// img (256,4,3,96,96) fp32, shift (256,2) int32 (sx=shift[b][0], sy=shift[b][1]).
//
// R3: warp-contiguous scalar mapping. One warp per image row (96 floats);
// lane l handles output columns l, l+32, l+64. Stores are aligned 128B
// warp-contiguous STG.32 (1 wavefront / 128B); loads are contiguous but
// misaligned by (sx-PAD)*4B (<=16B) -> <=2 wavefronts / 128B. Total ~2.9
// wf/128B vs ~5.5 (R1 strided scalar) and ~7 (R2 smem staging). No smem.

#define PAD 4
#define N_IMG 256
#define T_IMG 4
#define C_IMG 3
#define H_IMG 96
#define W_IMG 96
#define TC (T_IMG * C_IMG)                  // 12
#define TOTAL_ROWS (N_IMG * TC * H_IMG)     // 294912
#define WARPS_PER_BLOCK 8
#define THREADS (WARPS_PER_BLOCK * 32)

__global__ __launch_bounds__(THREADS) void shift_img_kernel(
    const float* __restrict__ img,
    const int*   __restrict__ shift,
    float*       __restrict__ out)
{
    const int warp = threadIdx.x >> 5;
    const int lane = threadIdx.x & 31;
    const int row  = blockIdx.x * WARPS_PER_BLOCK + warp;   // global output row
    // grid sized exactly: TOTAL_ROWS % WARPS_PER_BLOCK == 0

    const float INV255 = 1.0f / 255.0f;

    int i       = row % H_IMG;        // output row within plane
    int img_idx = row / H_IMG;        // flattened (b,t,c)
    int b       = img_idx / TC;

    int sx = __ldg(&shift[2 * b + 0]);
    int sy = __ldg(&shift[2 * b + 1]);

    int srcY = min(max(i + sy - PAD, 0), H_IMG - 1);
    int d    = sx - PAD;              // x displacement in [-4, 4]

    const float* src = img + (size_t)img_idx * (H_IMG * W_IMG) + (size_t)srcY * W_IMG;
    float*       dst = out + (size_t)row * W_IMG;

    #pragma unroll
    for (int c = 0; c < 3; c++) {
        int j = lane + 32 * c;
        int x = min(max(j + d, 0), W_IMG - 1);
        dst[j] = fmaf(__ldg(src + x), INV255, -0.5f);
    }
}

extern "C" void kernel_launch(void* const* d_in, const int* in_sizes, int n_in,
                              void* d_out, int out_size)
{
    const float* img   = (const float*)d_in[0];
    const int*   shift = (const int*)d_in[1];
    float*       out   = (float*)d_out;

    int blocks = TOTAL_ROWS / WARPS_PER_BLOCK;   // 36864
    shift_img_kernel<<<blocks, THREADS>>>(img, shift, out);
}

// round 4
// speedup vs baseline: 1.1987x; 1.1987x over previous
#include <cuda_runtime.h>
#include <cuda_bf16.h>

// ShiftImgPreprocessor: out[b,t,c,i,j] = img[b,t,c, clamp(i+sy-PAD,0,H-1),
//                                              clamp(j+sx-PAD,0,W-1)] / 255 - 0.5
// img (256,4,3,96,96) fp32, shift (256,2) int32 (sx=shift[b][0], sy=shift[b][1]).
//
// R4: warp-contiguous + deep MLP. Each warp handles 4 consecutive rows of ONE
// plane (96%4==0 so groups never straddle planes -> b/sx/sy/x-clamps computed
// once per warp). 12 independent scalar loads per lane are issued before any
// store (12-deep MLP vs 3 in R3); stores are aligned warp-contiguous STG.32.

#define PAD 4
#define N_IMG 256
#define T_IMG 4
#define C_IMG 3
#define H_IMG 96
#define W_IMG 96
#define TC (T_IMG * C_IMG)                    // 12 planes per batch
#define N_PLANES (N_IMG * TC)                 // 3072
#define ROWS_PER_WARP 4
#define WARPS_PER_BLOCK 8
#define THREADS (WARPS_PER_BLOCK * 32)
#define ROWS_PER_BLOCK (WARPS_PER_BLOCK * ROWS_PER_WARP)   // 32
#define TOTAL_ROWS (N_PLANES * H_IMG)         // 294912
#define NBLOCKS (TOTAL_ROWS / ROWS_PER_BLOCK) // 9216

__global__ __launch_bounds__(THREADS) void shift_img_kernel(
    const float* __restrict__ img,
    const int*   __restrict__ shift,
    float*       __restrict__ out)
{
    const int warp = threadIdx.x >> 5;
    const int lane = threadIdx.x & 31;
    const int base = blockIdx.x * ROWS_PER_BLOCK + warp * ROWS_PER_WARP; // first row

    const float INV255 = 1.0f / 255.0f;

    const int plane = base / H_IMG;          // flattened (b,t,c); same for all 4 rows
    const int i0    = base % H_IMG;
    const int b     = plane / TC;

    const int sx = __ldg(&shift[2 * b + 0]);
    const int sy = __ldg(&shift[2 * b + 1]);
    const int d  = sx - PAD;                 // in [-4, 4]

    // x source columns, shared by all 4 rows (computed once)
    int x0 = min(max(lane +  0 + d, 0), W_IMG - 1);
    int x1 = min(max(lane + 32 + d, 0), W_IMG - 1);
    int x2 = min(max(lane + 64 + d, 0), W_IMG - 1);

    const float* sp = img + (size_t)plane * (H_IMG * W_IMG);
    float*       dp = out + (size_t)base  * W_IMG;

    // y source rows
    int sY[ROWS_PER_WARP];
    #pragma unroll
    for (int k = 0; k < ROWS_PER_WARP; k++)
        sY[k] = min(max(i0 + k + sy - PAD, 0), H_IMG - 1);

    // ---- issue all 12 independent loads first (deep MLP) ----
    float v[ROWS_PER_WARP][3];
    #pragma unroll
    for (int k = 0; k < ROWS_PER_WARP; k++) {
        const float* r = sp + sY[k] * W_IMG;
        v[k][0] = __ldg(r + x0);
        v[k][1] = __ldg(r + x1);
        v[k][2] = __ldg(r + x2);
    }

    // ---- normalize + aligned contiguous stores ----
    #pragma unroll
    for (int k = 0; k < ROWS_PER_WARP; k++) {
        float* w = dp + k * W_IMG;
        w[lane +  0] = fmaf(v[k][0], INV255, -0.5f);
        w[lane + 32] = fmaf(v[k][1], INV255, -0.5f);
        w[lane + 64] = fmaf(v[k][2], INV255, -0.5f);
    }
}

extern "C" void kernel_launch(void* const* d_in, const int* in_sizes, int n_in,
                              void* d_out, int out_size)
{
    const float* img   = (const float*)d_in[0];
    const int*   shift = (const int*)d_in[1];
    float*       out   = (float*)d_out;

    shift_img_kernel<<<NBLOCKS, THREADS>>>(img, shift, out);
}